// round 4
// baseline (speedup 1.0000x reference)
#include <cuda_runtime.h>
#include <cstdint>

#define BATCH 4096
#define NST   512
#define IO    16
#define DS    32
#define PTOT  8192
#define NCH   32
#define LCH   16   // stages per chunk

typedef unsigned long long ull;   // f32x2 pair

// ---------------- scratch (device globals; no mallocs allowed) ----------------
__device__ float g_xloc[2][BATCH][NCH][DS];   // local chunk-exit states
__device__ float g_xin [2][BATCH][NCH][DS];   // chunk-entry states
__device__ float g_P   [2][NCH][DS*DS];       // chunk propagators
__device__ float g_ya  [BATCH*PTOT];          // anticausal local y
// packed pair-major weights (f32x2 units, stored as float[2*pairs]):
//   causal stage: A' [0,512) pairs (j*16+ip), C' [512,768) (j*8+ip),
//                 B' [768,1024) (j<16: j*16+ip), D' [1024,1152) (j<16: j*8+ip), bias [1152,1160)
__device__ __align__(16) float g_wc[NST][2320];
//   anti stage:   E' [0,512), F' [512,768) (j<16), G' [768,1024)
__device__ __align__(16) float g_wa[NST][2048];
//   fixup stage:  M' [0,256) pairs (j*8+ip), N' [256,512)
__device__ __align__(16) float g_mn[NST][1024];

// ---------------- f32x2 helpers ----------------
__device__ __forceinline__ ull pack2(float lo, float hi) {
    ull r; asm("mov.b64 %0, {%1, %2};" : "=l"(r) : "f"(lo), "f"(hi)); return r;
}
__device__ __forceinline__ ull dup2(float v) { return pack2(v, v); }
__device__ __forceinline__ void unpack2(ull p, float& lo, float& hi) {
    asm("mov.b64 {%0, %1}, %2;" : "=f"(lo), "=f"(hi) : "l"(p));
}
__device__ __forceinline__ ull fma2(ull a, ull b, ull c) {
    ull r; asm("fma.rn.f32x2 %0, %1, %2, %3;" : "=l"(r) : "l"(a), "l"(b), "l"(c)); return r;
}
__device__ __forceinline__ ull add2(ull a, ull b) {
    ull r; asm("add.rn.f32x2 %0, %1, %2;" : "=l"(r) : "l"(a), "l"(b)); return r;
}

// ---------------- cp.async helpers ----------------
__device__ __forceinline__ void cpasync16(void* s, const void* g) {
    uint32_t sa = (uint32_t)__cvta_generic_to_shared(s);
    asm volatile("cp.async.cg.shared.global [%0], [%1], 16;" :: "r"(sa), "l"(g));
}
__device__ __forceinline__ void cpcommit() { asm volatile("cp.async.commit_group;"); }
template<int N> __device__ __forceinline__ void cpwait() {
    asm volatile("cp.async.wait_group %0;" :: "n"(N));
}

// =====================================================================
// Repack raw weights into pair-major layout for f32x2 FMA.
// =====================================================================
__global__ void repack_kernel(const float* __restrict__ A, const float* __restrict__ B,
                              const float* __restrict__ C, const float* __restrict__ D,
                              const float* __restrict__ E, const float* __restrict__ F,
                              const float* __restrict__ G, const float* __restrict__ bias) {
    const int k = blockIdx.x, tid = threadIdx.x;
    float* wc = g_wc[k];
    float* wa = g_wa[k];
    // A,E (32x32): pairs [0,512): j = e>>4, ip = e&15
    for (int e = tid; e < 512; e += 256) {
        const int j = e >> 4, ip = e & 15;
        wc[2*e]   = A[(size_t)k*1024 + (2*ip)*32 + j];
        wc[2*e+1] = A[(size_t)k*1024 + (2*ip+1)*32 + j];
        wa[2*e]   = E[(size_t)k*1024 + (2*ip)*32 + j];
        wa[2*e+1] = E[(size_t)k*1024 + (2*ip+1)*32 + j];
    }
    // C (16x32) -> wc[512,768); G (16x32) -> wa[768,1024): j = e>>3, ip = e&7
    for (int e = tid; e < 256; e += 256) {
        const int j = e >> 3, ip = e & 7;
        wc[2*(512+e)]   = C[(size_t)k*512 + (2*ip)*32 + j];
        wc[2*(512+e)+1] = C[(size_t)k*512 + (2*ip+1)*32 + j];
        wa[2*(768+e)]   = G[(size_t)k*512 + (2*ip)*32 + j];
        wa[2*(768+e)+1] = G[(size_t)k*512 + (2*ip+1)*32 + j];
    }
    // B (32x16) -> wc[768,1024); F (32x16) -> wa[512,768): j = e>>4 (0..15), ip = e&15
    for (int e = tid; e < 256; e += 256) {
        const int j = e >> 4, ip = e & 15;
        wc[2*(768+e)]   = B[(size_t)k*512 + (2*ip)*16 + j];
        wc[2*(768+e)+1] = B[(size_t)k*512 + (2*ip+1)*16 + j];
        wa[2*(512+e)]   = F[(size_t)k*512 + (2*ip)*16 + j];
        wa[2*(512+e)+1] = F[(size_t)k*512 + (2*ip+1)*16 + j];
    }
    // D (16x16) -> wc[1024,1152): j = e>>3 (0..15), ip = e&7
    for (int e = tid; e < 128; e += 256) {
        const int j = e >> 3, ip = e & 7;
        wc[2*(1024+e)]   = D[(size_t)k*256 + (2*ip)*16 + j];
        wc[2*(1024+e)+1] = D[(size_t)k*256 + (2*ip+1)*16 + j];
    }
    // bias pairs [1152,1160)
    if (tid < 8) {
        wc[2*(1152+tid)]   = bias[k*16 + 2*tid];
        wc[2*(1152+tid)+1] = bias[k*16 + 2*tid + 1];
    }
}

// =====================================================================
// Precompute per (dir, chunk): M_k = C_k Phi_k (packed into g_mn) and P_c.
// =====================================================================
__global__ void precompute_kernel(const float* __restrict__ A, const float* __restrict__ C,
                                  const float* __restrict__ E, const float* __restrict__ G) {
    __shared__ float Phi[2][DS*DS];
    const int tid = threadIdx.x;
    const int c = blockIdx.x, d = blockIdx.y;

    for (int i = tid; i < DS*DS; i += 256) Phi[0][i] = ((i >> 5) == (i & 31)) ? 1.f : 0.f;
    __syncthreads();

    int pb = 0;
    for (int t = 0; t < LCH; ++t) {
        const int k = (d == 0) ? (c*LCH + t) : (c*LCH + LCH-1 - t);
        const float* W1 = (d == 0) ? (C + k*IO*DS) : (G + k*IO*DS);   // 16x32
        const float* W2 = (d == 0) ? (A + k*DS*DS) : (E + k*DS*DS);   // 32x32

        // M_k = W1 * Phi, packed pair-major into g_mn (M at [0,256), N at [256,512) pairs)
        for (int e = tid; e < IO*DS; e += 256) {
            const int i = e >> 5, j = e & 31;
            float acc = 0.f;
#pragma unroll
            for (int l = 0; l < DS; ++l) acc += W1[i*DS + l] * Phi[pb][l*DS + j];
            g_mn[k][(d*256 + j*8 + (i >> 1))*2 + (i & 1)] = acc;
        }
        // Phi_new = W2 * Phi
        for (int e = tid; e < DS*DS; e += 256) {
            const int i = e >> 5, j = e & 31;
            float acc = 0.f;
#pragma unroll
            for (int l = 0; l < DS; ++l) acc += W2[i*DS + l] * Phi[pb][l*DS + j];
            Phi[pb^1][e] = acc;
        }
        __syncthreads();
        pb ^= 1;
    }
    for (int e = tid; e < DS*DS; e += 256) g_P[d][c][e] = Phi[pb][e];
}

// =====================================================================
// Phase A: local chunk scans, f32x2 pair-math. One thread per row.
// =====================================================================
__global__ __launch_bounds__(256, 2)
void phaseA_kernel(const float* __restrict__ U, float* __restrict__ out) {
    __shared__ float4 swb[2][580];

    const int tid = threadIdx.x;
    const int c = blockIdx.y, d = blockIdx.z;
    const int row = blockIdx.x * 256 + tid;
    const int k0 = c * LCH;
    const int nldg = (d == 0) ? 580 : 512;

    auto stage_k = [&](int t) { return (d == 0) ? (k0 + t) : (k0 + LCH-1 - t); };
    auto load_stage = [&](float4* dst, int k) {
        const float4* src = (d == 0) ? (const float4*)g_wc[k] : (const float4*)g_wa[k];
        for (int i = tid; i < nldg; i += 256) cpasync16(dst + i, src + i);
    };

    load_stage(swb[0], stage_k(0)); cpcommit();
    load_stage(swb[1], stage_k(1)); cpcommit();

    float x[DS];

#pragma unroll 1
    for (int t = 0; t < LCH; ++t) {
        cpwait<1>();
        __syncthreads();
        const ull* wp = (const ull*)swb[t & 1];
        const int k = stage_k(t);
        const size_t off = (size_t)row * PTOT + (size_t)k * IO;

        float u[IO];
        {
            const float4* up = (const float4*)(U + off);
#pragma unroll
            for (int m = 0; m < 4; ++m) {
                float4 v = up[m];
                u[4*m] = v.x; u[4*m+1] = v.y; u[4*m+2] = v.z; u[4*m+3] = v.w;
            }
        }

        ull accx[16], accy[8];
#pragma unroll
        for (int ip = 0; ip < 16; ++ip) accx[ip] = 0ull;
        if (d == 0) {
#pragma unroll
            for (int ip = 0; ip < 8; ++ip) accy[ip] = wp[1152 + ip];   // bias
        } else {
#pragma unroll
            for (int ip = 0; ip < 8; ++ip) accy[ip] = 0ull;
        }

        if (t != 0) {
            // state contributions: x'/z' += A/E x ; y += C/G x
#pragma unroll
            for (int j = 0; j < DS; ++j) {
                const ull xx = dup2(x[j]);
                const ulonglong2* Ab = (const ulonglong2*)(wp + j*16);
#pragma unroll
                for (int q = 0; q < 8; ++q) {
                    ulonglong2 av = Ab[q];
                    accx[2*q]   = fma2(av.x, xx, accx[2*q]);
                    accx[2*q+1] = fma2(av.y, xx, accx[2*q+1]);
                }
                const ulonglong2* Cb = (const ulonglong2*)(wp + ((d == 0) ? 512 : 768) + j*8);
#pragma unroll
                for (int q = 0; q < 4; ++q) {
                    ulonglong2 cv = Cb[q];
                    accy[2*q]   = fma2(cv.x, xx, accy[2*q]);
                    accy[2*q+1] = fma2(cv.y, xx, accy[2*q+1]);
                }
            }
        }

        // input contributions: x' += B/F u ; causal y += D u
        const int boff = (d == 0) ? 768 : 512;
#pragma unroll
        for (int j = 0; j < IO; ++j) {
            const ull uu = dup2(u[j]);
            const ulonglong2* Bb = (const ulonglong2*)(wp + boff + j*16);
#pragma unroll
            for (int q = 0; q < 8; ++q) {
                ulonglong2 bv = Bb[q];
                accx[2*q]   = fma2(bv.x, uu, accx[2*q]);
                accx[2*q+1] = fma2(bv.y, uu, accx[2*q+1]);
            }
            if (d == 0) {
                const ulonglong2* Db = (const ulonglong2*)(wp + 1024 + j*8);
#pragma unroll
                for (int q = 0; q < 4; ++q) {
                    ulonglong2 dv = Db[q];
                    accy[2*q]   = fma2(dv.x, uu, accy[2*q]);
                    accy[2*q+1] = fma2(dv.y, uu, accy[2*q+1]);
                }
            }
        }

        // write y (pairs are consecutive in memory)
        {
            ull* oq = (ull*)(((d == 0) ? out : g_ya) + off);
#pragma unroll
            for (int m = 0; m < 8; ++m) oq[m] = accy[m];
        }

        // unpack state for next stage
#pragma unroll
        for (int ip = 0; ip < 16; ++ip) unpack2(accx[ip], x[2*ip], x[2*ip+1]);

        __syncthreads();
        if (t + 2 < LCH) load_stage(swb[t & 1], stage_k(t + 2));
        cpcommit();
    }

    float4* xo = (float4*)&g_xloc[d][row][c][0];
#pragma unroll
    for (int m = 0; m < 8; ++m)
        xo[m] = make_float4(x[4*m], x[4*m+1], x[4*m+2], x[4*m+3]);
}

// =====================================================================
// Phase B: sequential chunk recombination per row. One warp per (row, dir).
// =====================================================================
__global__ __launch_bounds__(256)
void phaseB_kernel() {
    __shared__ float sP[DS*DS];
    const int tid = threadIdx.x, lane = tid & 31, wp = tid >> 5;
    const int d = blockIdx.x >> 9;                  // 512 CTAs per direction
    const int row = ((blockIdx.x & 511) << 3) + wp;

    float x = 0.f;
    for (int ci = 0; ci < NCH; ++ci) {
        const int c = (d == 0) ? ci : (NCH-1 - ci);
        __syncthreads();
        for (int i = tid; i < DS*DS; i += 256) sP[i] = g_P[d][c][i];
        __syncthreads();

        g_xin[d][row][c][lane] = x;
        float acc = g_xloc[d][row][c][lane];
        const float* pr = &sP[lane * DS];
#pragma unroll
        for (int j = 0; j < DS; ++j) {
            const int jj = (j + lane) & 31;
            acc += pr[jj] * __shfl_sync(0xffffffffu, x, jj);
        }
        x = acc;
    }
}

// =====================================================================
// Fixup: out = y_c + y_a + M_k x_in + N_k z_in  (f32x2 pair-math)
// =====================================================================
__global__ __launch_bounds__(256, 2)
void fixup_kernel(float* __restrict__ out) {
    __shared__ float4 smb[2][256];
    const int tid = threadIdx.x;
    const int c = blockIdx.y;
    const int row = blockIdx.x * 256 + tid;
    const int k0 = c * LCH;

    auto load_mn = [&](float4* dst, int k) {
        cpasync16(dst + tid, (const float4*)g_mn[k] + tid);
    };
    load_mn(smb[0], k0);     cpcommit();
    load_mn(smb[1], k0 + 1); cpcommit();

    float xin[DS], zin[DS];
    {
        const float4* xi = (const float4*)&g_xin[0][row][c][0];
        const float4* zi = (const float4*)&g_xin[1][row][c][0];
#pragma unroll
        for (int m = 0; m < 8; ++m) {
            float4 a = xi[m]; xin[4*m]=a.x; xin[4*m+1]=a.y; xin[4*m+2]=a.z; xin[4*m+3]=a.w;
            float4 b = zi[m]; zin[4*m]=b.x; zin[4*m+1]=b.y; zin[4*m+2]=b.z; zin[4*m+3]=b.w;
        }
    }

#pragma unroll 1
    for (int s = 0; s < LCH; ++s) {
        cpwait<1>();
        __syncthreads();
        const ull* wp = (const ull*)smb[s & 1];
        const int k = k0 + s;
        const size_t off = (size_t)row * PTOT + (size_t)k * IO;

        ull accy[8];
        {
            const ull* oq = (const ull*)(out + off);
            const ull* aq = (const ull*)(g_ya + off);
#pragma unroll
            for (int m = 0; m < 8; ++m) accy[m] = add2(oq[m], aq[m]);
        }

#pragma unroll
        for (int j = 0; j < DS; ++j) {
            const ull xx = dup2(xin[j]);
            const ulonglong2* Mb = (const ulonglong2*)(wp + j*8);
#pragma unroll
            for (int q = 0; q < 4; ++q) {
                ulonglong2 mv = Mb[q];
                accy[2*q]   = fma2(mv.x, xx, accy[2*q]);
                accy[2*q+1] = fma2(mv.y, xx, accy[2*q+1]);
            }
            const ull zz = dup2(zin[j]);
            const ulonglong2* Nb = (const ulonglong2*)(wp + 256 + j*8);
#pragma unroll
            for (int q = 0; q < 4; ++q) {
                ulonglong2 nv = Nb[q];
                accy[2*q]   = fma2(nv.x, zz, accy[2*q]);
                accy[2*q+1] = fma2(nv.y, zz, accy[2*q+1]);
            }
        }

        {
            ull* oq = (ull*)(out + off);
#pragma unroll
            for (int m = 0; m < 8; ++m) oq[m] = accy[m];
        }

        __syncthreads();
        if (s + 2 < LCH) load_mn(smb[s & 1], k0 + s + 2);
        cpcommit();
    }
}

// =====================================================================
extern "C" void kernel_launch(void* const* d_in, const int* in_sizes, int n_in,
                              void* d_out, int out_size) {
    const float* U    = (const float*)d_in[0];
    const float* A    = (const float*)d_in[1];
    const float* B    = (const float*)d_in[2];
    const float* C    = (const float*)d_in[3];
    const float* D    = (const float*)d_in[4];
    const float* E    = (const float*)d_in[5];
    const float* F    = (const float*)d_in[6];
    const float* G    = (const float*)d_in[7];
    const float* bias = (const float*)d_in[8];
    float* out = (float*)d_out;

    repack_kernel<<<NST, 256>>>(A, B, C, D, E, F, G, bias);
    precompute_kernel<<<dim3(NCH, 2), 256>>>(A, C, E, G);
    phaseA_kernel<<<dim3(BATCH/256, NCH, 2), 256>>>(U, out);
    phaseB_kernel<<<1024, 256>>>();
    fixup_kernel<<<dim3(BATCH/256, NCH), 256>>>(out);
}

// round 5
// speedup vs baseline: 1.8048x; 1.8048x over previous
#include <cuda_runtime.h>
#include <cstdint>

#define BATCH 4096
#define NST   512
#define IO    16
#define DS    32
#define PTOT  8192
#define NCH   32
#define LCH   16

typedef unsigned long long ull;

// ---------------- device scratch (static; no mallocs) ----------------
__device__ float g_Ut[(size_t)PTOT * BATCH];          // U transposed [p][row]   128MB
__device__ float g_T [(size_t)NCH * 320 * 256];       // GEMM2 B-matrix per chunk
__device__ float g_S [(size_t)NCH * 256 * 64];        // GEMM1 B-matrix per chunk
__device__ float g_xlocT[2][NCH][DS][BATCH];          // chunk-local exit states (transposed)
__device__ float g_xinT [2][NCH][DS][BATCH];          // chunk-entry states (transposed)
__device__ float g_P2[2 * NCH * DS * DS];             // propagators, pair-major transposed

// ---------------- f32x2 helpers ----------------
__device__ __forceinline__ ull pack2(float lo, float hi) {
    ull r; asm("mov.b64 %0, {%1, %2};" : "=l"(r) : "f"(lo), "f"(hi)); return r;
}
__device__ __forceinline__ ull dup2(float v) { return pack2(v, v); }
__device__ __forceinline__ void unpack2(ull p, float& lo, float& hi) {
    asm("mov.b64 {%0, %1}, %2;" : "=f"(lo), "=f"(hi) : "l"(p));
}
__device__ __forceinline__ ull fma2(ull a, ull b, ull c) {
    ull r; asm("fma.rn.f32x2 %0, %1, %2, %3;" : "=l"(r) : "l"(a), "l"(b), "l"(c)); return r;
}
__device__ __forceinline__ ull add2(ull a, ull b) {
    ull r; asm("add.rn.f32x2 %0, %1, %2;" : "=l"(r) : "l"(a), "l"(b)); return r;
}

// ---------------- cp.async helpers ----------------
__device__ __forceinline__ void cpasync16(void* s, const void* g) {
    uint32_t sa = (uint32_t)__cvta_generic_to_shared(s);
    asm volatile("cp.async.cg.shared.global [%0], [%1], 16;" :: "r"(sa), "l"(g));
}
__device__ __forceinline__ void cpcommit() { asm volatile("cp.async.commit_group;"); }
template<int N> __device__ __forceinline__ void cpwait() {
    asm volatile("cp.async.wait_group %0;" :: "n"(N));
}

// =====================================================================
// 1. Transpose U -> Ut
// =====================================================================
__global__ void transpose_kernel(const float* __restrict__ U) {
    __shared__ float t[32][33];
    const int bx = blockIdx.x * 32;   // p dim
    const int by = blockIdx.y * 32;   // row dim
    const int tx = threadIdx.x, ty = threadIdx.y;
#pragma unroll
    for (int j = 0; j < 32; j += 8)
        t[ty + j][tx] = U[(size_t)(by + ty + j) * PTOT + bx + tx];
    __syncthreads();
#pragma unroll
    for (int j = 0; j < 32; j += 8)
        g_Ut[(size_t)(bx + ty + j) * BATCH + by + tx] = t[tx][ty + j];
}

// =====================================================================
// 2. Strip precompute: per (chunk, strip s, dir) build T input-blocks + S cols
// =====================================================================
__global__ __launch_bounds__(128)
void strip_kernel(const float* __restrict__ A, const float* __restrict__ B,
                  const float* __restrict__ C, const float* __restrict__ D,
                  const float* __restrict__ E, const float* __restrict__ F,
                  const float* __restrict__ G) {
    __shared__ float sV[2][DS][IO];
    __shared__ float sW2[DS][DS];
    __shared__ float sW1[IO][DS];
    const int tid = threadIdx.x;
    const int c = blockIdx.x, s = blockIdx.y, d = blockIdx.z;
    const int k0 = c * LCH;
    float* Tc = g_T + (size_t)c * 320 * 256;

    const float* src0 = ((d == 0) ? B : F) + (size_t)(k0 + s) * 512;
    for (int e = tid; e < 512; e += 128) sV[0][e >> 4][e & 15] = src0[e];
    if (d == 0) {   // diagonal block = D_s
        const float* Ds = D + (size_t)(k0 + s) * 256;
        for (int e = tid; e < 256; e += 128) {
            const int o = e >> 4, i = e & 15;
            Tc[(s * 16 + i) * 256 + s * 16 + o] = Ds[o * 16 + i];
        }
    }
    __syncthreads();

    int pb = 0;
    const int nsteps = (d == 0) ? (LCH - 1 - s) : s;
    for (int step = 0; step < nsteps; ++step) {
        const int t = (d == 0) ? (s + 1 + step) : (s - 1 - step);
        const int k = k0 + t;
        const float* W2 = ((d == 0) ? A : E) + (size_t)k * 1024;
        const float* W1 = ((d == 0) ? C : G) + (size_t)k * 512;
        for (int e = tid; e < 1024; e += 128) sW2[e >> 5][e & 31] = W2[e];
        for (int e = tid; e < 512;  e += 128) sW1[e >> 5][e & 31] = W1[e];
        __syncthreads();
        for (int e = tid; e < 256; e += 128) {
            const int o = e >> 4, i = e & 15;
            float acc = 0.f;
#pragma unroll
            for (int l = 0; l < DS; ++l) acc += sW1[o][l] * sV[pb][l][i];
            Tc[(s * 16 + i) * 256 + t * 16 + o] = acc;
        }
        for (int e = tid; e < 512; e += 128) {
            const int j = e >> 4, i = e & 15;
            float acc = 0.f;
#pragma unroll
            for (int l = 0; l < DS; ++l) acc += sW2[j][l] * sV[pb][l][i];
            sV[pb ^ 1][j][i] = acc;
        }
        __syncthreads();
        pb ^= 1;
    }
    // S column strip: final V
    for (int e = tid; e < 512; e += 128) {
        const int j = e >> 4, i = e & 15;
        g_S[(size_t)c * 256 * 64 + (s * 16 + i) * 64 + d * 32 + j] = sV[pb][j][i];
    }
}

// =====================================================================
// 3. M/N strips + propagators per (chunk, dir)
// =====================================================================
__global__ __launch_bounds__(256)
void mn_kernel(const float* __restrict__ A, const float* __restrict__ C,
               const float* __restrict__ E, const float* __restrict__ G) {
    __shared__ float sV[2][DS][DS];
    __shared__ float sW2[DS][DS];
    __shared__ float sW1[IO][DS];
    const int tid = threadIdx.x;
    const int c = blockIdx.x, d = blockIdx.y;
    const int k0 = c * LCH;
    float* Tc = g_T + (size_t)c * 320 * 256;

    for (int e = tid; e < 1024; e += 256)
        sV[0][e >> 5][e & 31] = ((e >> 5) == (e & 31)) ? 1.f : 0.f;
    __syncthreads();

    int pb = 0;
    for (int step = 0; step < LCH; ++step) {
        const int t = (d == 0) ? step : (LCH - 1 - step);
        const int k = k0 + t;
        const float* W2 = ((d == 0) ? A : E) + (size_t)k * 1024;
        const float* W1 = ((d == 0) ? C : G) + (size_t)k * 512;
        for (int e = tid; e < 1024; e += 256) sW2[e >> 5][e & 31] = W2[e];
        for (int e = tid; e < 512;  e += 256) sW1[e >> 5][e & 31] = W1[e];
        __syncthreads();
        for (int e = tid; e < 512; e += 256) {
            const int o = e >> 5, j = e & 31;
            float acc = 0.f;
#pragma unroll
            for (int l = 0; l < DS; ++l) acc += sW1[o][l] * sV[pb][l][j];
            Tc[(256 + d * 32 + j) * 256 + t * 16 + o] = acc;
        }
        for (int e = tid; e < 1024; e += 256) {
            const int i = e >> 5, j = e & 31;
            float acc = 0.f;
#pragma unroll
            for (int l = 0; l < DS; ++l) acc += sW2[i][l] * sV[pb][l][j];
            sV[pb ^ 1][i][j] = acc;
        }
        __syncthreads();
        pb ^= 1;
    }
    // store propagator transposed (pair-major over i): g_P2[..][j*32+i] = V[i][j]
    for (int e = tid; e < 1024; e += 256) {
        const int i = e >> 5, j = e & 31;
        g_P2[(size_t)(d * NCH + c) * 1024 + j * 32 + i] = sV[pb][i][j];
    }
}

// =====================================================================
// 4. GEMM1: xloc/zloc[64] = Ut_chunk[256] x S_c   (M=4096, K=256, N=64)
// =====================================================================
__global__ __launch_bounds__(256, 2)
void gemm1_kernel() {
    __shared__ float sA[32 * 128];
    __shared__ float sB[32 * 64];
    const int tid = threadIdx.x;
    const int mt = blockIdx.x, c = blockIdx.y;
    const int row0 = mt * 128;
    const int wid = tid >> 5, lane = tid & 31;
    const int warp_m = wid & 3, warp_n = wid >> 2;
    const int mg = lane >> 3, ng = lane & 7;
    const int m0 = warp_m * 32 + mg * 8, n0 = warp_n * 32 + ng * 4;

    ull acc[8][2];
#pragma unroll
    for (int i = 0; i < 8; ++i) { acc[i][0] = 0; acc[i][1] = 0; }
    const float* Sc = g_S + (size_t)c * 256 * 64;

#pragma unroll 1
    for (int kt = 0; kt < 8; ++kt) {
        if (kt) __syncthreads();
#pragma unroll
        for (int q = 0; q < 4; ++q) {
            const int idx = tid + 256 * q, k = idx >> 5, m4 = idx & 31;
            cpasync16(&sA[k * 128 + m4 * 4],
                      g_Ut + (size_t)(c * 256 + kt * 32 + k) * BATCH + row0 + m4 * 4);
        }
#pragma unroll
        for (int q = 0; q < 2; ++q) {
            const int idx = tid + 256 * q, k = idx >> 4, n4 = idx & 15;
            cpasync16(&sB[k * 64 + n4 * 4], Sc + (kt * 32 + k) * 64 + n4 * 4);
        }
        cpcommit(); cpwait<0>(); __syncthreads();
#pragma unroll
        for (int k = 0; k < 32; ++k) {
            const float4 a0 = *(const float4*)&sA[k * 128 + m0];
            const float4 a1 = *(const float4*)&sA[k * 128 + m0 + 4];
            const ulonglong2 b = *(const ulonglong2*)&sB[k * 64 + n0];
            const float am[8] = {a0.x, a0.y, a0.z, a0.w, a1.x, a1.y, a1.z, a1.w};
#pragma unroll
            for (int mi = 0; mi < 8; ++mi) {
                const ull ax = dup2(am[mi]);
                acc[mi][0] = fma2(b.x, ax, acc[mi][0]);
                acc[mi][1] = fma2(b.y, ax, acc[mi][1]);
            }
        }
    }
    // epilogue: write column-major xlocT
#pragma unroll
    for (int q = 0; q < 2; ++q) {
#pragma unroll
        for (int h = 0; h < 2; ++h) {
            const int n = n0 + 2 * q + h;
            const int dd = n >> 5, j = n & 31;
            float v[8];
#pragma unroll
            for (int mi = 0; mi < 8; ++mi) {
                float lo, hi; unpack2(acc[mi][q], lo, hi);
                v[mi] = h ? hi : lo;
            }
            float* dst = &g_xlocT[dd][c][j][row0 + m0];
            *(float4*)dst       = make_float4(v[0], v[1], v[2], v[3]);
            *(float4*)(dst + 4) = make_float4(v[4], v[5], v[6], v[7]);
        }
    }
}

// =====================================================================
// 5. Phase B: sequential chunk recombination, one thread per row.
// =====================================================================
__global__ __launch_bounds__(64)
void phaseB_kernel() {
    __shared__ float sP[DS * DS];
    const int tid = threadIdx.x;
    const int d = blockIdx.y;
    const int row = blockIdx.x * 64 + tid;

    ull xp[16];
#pragma unroll
    for (int ip = 0; ip < 16; ++ip) xp[ip] = 0;

#pragma unroll 1
    for (int ci = 0; ci < NCH; ++ci) {
        const int c = d ? (NCH - 1 - ci) : ci;
        __syncthreads();
        {
            const float4* src = (const float4*)(g_P2 + (size_t)(d * NCH + c) * 1024);
#pragma unroll
            for (int q = 0; q < 4; ++q) ((float4*)sP)[tid + 64 * q] = src[tid + 64 * q];
        }
        __syncthreads();

        float x[DS];
#pragma unroll
        for (int ip = 0; ip < 16; ++ip) {
            unpack2(xp[ip], x[2 * ip], x[2 * ip + 1]);
            g_xinT[d][c][2 * ip][row]     = x[2 * ip];
            g_xinT[d][c][2 * ip + 1][row] = x[2 * ip + 1];
        }

        ull acc[16];
#pragma unroll
        for (int ip = 0; ip < 16; ++ip)
            acc[ip] = pack2(g_xlocT[d][c][2 * ip][row], g_xlocT[d][c][2 * ip + 1][row]);

#pragma unroll
        for (int j = 0; j < DS; ++j) {
            const ull xx = dup2(x[j]);
            const ulonglong2* pr = (const ulonglong2*)&sP[j * DS];
#pragma unroll
            for (int t = 0; t < 8; ++t) {
                const ulonglong2 pv = pr[t];
                acc[2 * t]     = fma2(pv.x, xx, acc[2 * t]);
                acc[2 * t + 1] = fma2(pv.y, xx, acc[2 * t + 1]);
            }
        }
#pragma unroll
        for (int ip = 0; ip < 16; ++ip) xp[ip] = acc[ip];
    }
}

// =====================================================================
// 6. GEMM2: out = [U_c | x_in | z_in](320) x T_c(320x256) + bias
// =====================================================================
__global__ __launch_bounds__(256, 2)
void gemm2_kernel(const float* __restrict__ bias, float* __restrict__ out) {
    __shared__ float sA[32 * 128];
    __shared__ float sB[32 * 128];
    const int tid = threadIdx.x;
    const int mt = blockIdx.x, nt = blockIdx.y, c = blockIdx.z;
    const int row0 = mt * 128, nc = nt * 128;
    const int wid = tid >> 5, lane = tid & 31;
    const int warp_m = wid & 3, warp_n = wid >> 2;
    const int mg = lane >> 3, ng = lane & 7;
    const int m0 = warp_m * 32 + mg * 8, n0 = warp_n * 64 + ng * 8;

    ull acc[8][4];
#pragma unroll
    for (int i = 0; i < 8; ++i)
#pragma unroll
        for (int q = 0; q < 4; ++q) acc[i][q] = 0;

    const float* Tc = g_T + (size_t)c * 320 * 256;

#pragma unroll 1
    for (int kt = 0; kt < 10; ++kt) {
        if (kt) __syncthreads();
#pragma unroll
        for (int q = 0; q < 4; ++q) {
            const int idx = tid + 256 * q, k = idx >> 5, m4 = idx & 31;
            const float* src = (kt < 8)
                ? g_Ut + (size_t)(c * 256 + kt * 32 + k) * BATCH + row0 + m4 * 4
                : &g_xinT[kt - 8][c][k][row0 + m4 * 4];
            cpasync16(&sA[k * 128 + m4 * 4], src);
        }
#pragma unroll
        for (int q = 0; q < 4; ++q) {
            const int idx = tid + 256 * q, k = idx >> 5, n4 = idx & 31;
            cpasync16(&sB[k * 128 + n4 * 4], Tc + (kt * 32 + k) * 256 + nc + n4 * 4);
        }
        cpcommit(); cpwait<0>(); __syncthreads();
#pragma unroll
        for (int k = 0; k < 32; ++k) {
            const float4 a0 = *(const float4*)&sA[k * 128 + m0];
            const float4 a1 = *(const float4*)&sA[k * 128 + m0 + 4];
            const ulonglong2 b0 = *(const ulonglong2*)&sB[k * 128 + n0];
            const ulonglong2 b1 = *(const ulonglong2*)&sB[k * 128 + n0 + 4];
            const float am[8] = {a0.x, a0.y, a0.z, a0.w, a1.x, a1.y, a1.z, a1.w};
#pragma unroll
            for (int mi = 0; mi < 8; ++mi) {
                const ull ax = dup2(am[mi]);
                acc[mi][0] = fma2(b0.x, ax, acc[mi][0]);
                acc[mi][1] = fma2(b0.y, ax, acc[mi][1]);
                acc[mi][2] = fma2(b1.x, ax, acc[mi][2]);
                acc[mi][3] = fma2(b1.y, ax, acc[mi][3]);
            }
        }
    }

    // epilogue: + bias, store
    const ull* bp = (const ull*)(bias + c * 256 + nc + n0);
    const ull bv0 = bp[0], bv1 = bp[1], bv2 = bp[2], bv3 = bp[3];
#pragma unroll
    for (int mi = 0; mi < 8; ++mi) {
        ull r0 = add2(acc[mi][0], bv0);
        ull r1 = add2(acc[mi][1], bv1);
        ull r2 = add2(acc[mi][2], bv2);
        ull r3 = add2(acc[mi][3], bv3);
        float* op = out + (size_t)(row0 + m0 + mi) * PTOT + c * 256 + nc + n0;
        ulonglong2 s0; s0.x = r0; s0.y = r1;
        ulonglong2 s1; s1.x = r2; s1.y = r3;
        *(ulonglong2*)op       = s0;
        *(ulonglong2*)(op + 4) = s1;
    }
}

// =====================================================================
extern "C" void kernel_launch(void* const* d_in, const int* in_sizes, int n_in,
                              void* d_out, int out_size) {
    const float* U    = (const float*)d_in[0];
    const float* A    = (const float*)d_in[1];
    const float* B    = (const float*)d_in[2];
    const float* C    = (const float*)d_in[3];
    const float* D    = (const float*)d_in[4];
    const float* E    = (const float*)d_in[5];
    const float* F    = (const float*)d_in[6];
    const float* G    = (const float*)d_in[7];
    const float* bias = (const float*)d_in[8];
    float* out = (float*)d_out;

    transpose_kernel<<<dim3(PTOT / 32, BATCH / 32), dim3(32, 8)>>>(U);
    strip_kernel<<<dim3(NCH, LCH, 2), 128>>>(A, B, C, D, E, F, G);
    mn_kernel<<<dim3(NCH, 2), 256>>>(A, C, E, G);
    gemm1_kernel<<<dim3(BATCH / 128, NCH), 256>>>();
    phaseB_kernel<<<dim3(BATCH / 64, 2), 64>>>();
    gemm2_kernel<<<dim3(BATCH / 128, 2, NCH), 256>>>(bias, out);
}

// round 7
// speedup vs baseline: 2.9718x; 1.6466x over previous
#include <cuda_runtime.h>
#include <cuda_bf16.h>
#include <cstdint>

#define BATCH 4096
#define NST   512
#define IO    16
#define DS    32
#define PTOT  8192
#define NCH   32
#define LCH   16

typedef unsigned long long ull;

// ---------------- device scratch (static; no mallocs) ----------------
__device__ __align__(16) __nv_bfloat16 g_Uh[(size_t)BATCH * PTOT];
__device__ __align__(16) __nv_bfloat16 g_Ul[(size_t)BATCH * PTOT];
__device__ __align__(16) __nv_bfloat16 g_Th[(size_t)NCH * 256 * 320];  // T^T per chunk [n][k]
__device__ __align__(16) __nv_bfloat16 g_Tl[(size_t)NCH * 256 * 320];
__device__ __align__(16) __nv_bfloat16 g_Sh[(size_t)NCH * 64 * 256];   // S^T per chunk [n][k]
__device__ __align__(16) __nv_bfloat16 g_Sl[(size_t)NCH * 64 * 256];
__device__ __align__(16) float g_xloc[(size_t)BATCH * NCH * 64];       // [row][c][64]
__device__ __align__(16) __nv_bfloat16 g_xinh[(size_t)BATCH * NCH * 64];
__device__ __align__(16) __nv_bfloat16 g_xinl[(size_t)BATCH * NCH * 64];
__device__ float g_P2[2 * NCH * DS * DS];

// ---------------- f32x2 helpers ----------------
__device__ __forceinline__ ull pack2(float lo, float hi) {
    ull r; asm("mov.b64 %0, {%1, %2};" : "=l"(r) : "f"(lo), "f"(hi)); return r;
}
__device__ __forceinline__ ull dup2(float v) { return pack2(v, v); }
__device__ __forceinline__ void unpack2(ull p, float& lo, float& hi) {
    asm("mov.b64 {%0, %1}, %2;" : "=f"(lo), "=f"(hi) : "l"(p));
}
__device__ __forceinline__ ull fma2(ull a, ull b, ull c) {
    ull r; asm("fma.rn.f32x2 %0, %1, %2, %3;" : "=l"(r) : "l"(a), "l"(b), "l"(c)); return r;
}

// ---------------- cp.async helpers ----------------
__device__ __forceinline__ void cpasync16(void* s, const void* g) {
    uint32_t sa = (uint32_t)__cvta_generic_to_shared(s);
    asm volatile("cp.async.cg.shared.global [%0], [%1], 16;" :: "r"(sa), "l"(g));
}
__device__ __forceinline__ void cpcommit() { asm volatile("cp.async.commit_group;"); }
template<int N> __device__ __forceinline__ void cpwait() {
    asm volatile("cp.async.wait_group %0;" :: "n"(N));
}

// ---------------- mma.sync / ldmatrix helpers ----------------
__device__ __forceinline__ void ldmx4(uint32_t* r, uint32_t addr) {
    asm volatile("ldmatrix.sync.aligned.m8n8.x4.shared.b16 {%0,%1,%2,%3}, [%4];"
        : "=r"(r[0]), "=r"(r[1]), "=r"(r[2]), "=r"(r[3]) : "r"(addr));
}
__device__ __forceinline__ void ldmx2(uint32_t* r, uint32_t addr) {
    asm volatile("ldmatrix.sync.aligned.m8n8.x2.shared.b16 {%0,%1}, [%2];"
        : "=r"(r[0]), "=r"(r[1]) : "r"(addr));
}
__device__ __forceinline__ void mma16816(float* c, const uint32_t* a, const uint32_t* b) {
    asm volatile(
        "mma.sync.aligned.m16n8k16.row.col.f32.bf16.bf16.f32 "
        "{%0,%1,%2,%3}, {%4,%5,%6,%7}, {%8,%9}, {%0,%1,%2,%3};"
        : "+f"(c[0]), "+f"(c[1]), "+f"(c[2]), "+f"(c[3])
        : "r"(a[0]), "r"(a[1]), "r"(a[2]), "r"(a[3]), "r"(b[0]), "r"(b[1]));
}
// swizzled smem offset: logical (row r, 16B chunk k8) in a [*,64]bf16 tile
__device__ __forceinline__ uint32_t swz(int r, int k8) {
    return (uint32_t)(r * 128 + ((k8 ^ (r & 7)) << 4));
}

__device__ __forceinline__ void split_bf16(float v, __nv_bfloat16& h, __nv_bfloat16& l) {
    h = __float2bfloat16(v);
    l = __float2bfloat16(v - __bfloat162float(h));
}

// =====================================================================
// 1. Split U -> Uh, Ul
// =====================================================================
__global__ __launch_bounds__(256)
void convertU_kernel(const float* __restrict__ U) {
    const size_t i = (size_t)blockIdx.x * 256 + threadIdx.x;
    const float4 v = ((const float4*)U)[i];
    __nv_bfloat16 h0, h1, h2, h3, l0, l1, l2, l3;
    split_bf16(v.x, h0, l0); split_bf16(v.y, h1, l1);
    split_bf16(v.z, h2, l2); split_bf16(v.w, h3, l3);
    ((__nv_bfloat162*)g_Uh)[2*i]   = __nv_bfloat162(h0, h1);
    ((__nv_bfloat162*)g_Uh)[2*i+1] = __nv_bfloat162(h2, h3);
    ((__nv_bfloat162*)g_Ul)[2*i]   = __nv_bfloat162(l0, l1);
    ((__nv_bfloat162*)g_Ul)[2*i+1] = __nv_bfloat162(l2, l3);
}

// =====================================================================
// 2. Strip precompute -> T^T (bf16 h/l) input blocks + S^T columns
// =====================================================================
__global__ __launch_bounds__(128)
void strip_kernel(const float* __restrict__ A, const float* __restrict__ B,
                  const float* __restrict__ C, const float* __restrict__ D,
                  const float* __restrict__ E, const float* __restrict__ F,
                  const float* __restrict__ G) {
    __shared__ float sV[2][DS][IO];
    __shared__ float sW2[DS][DS];
    __shared__ float sW1[IO][DS];
    const int tid = threadIdx.x;
    const int c = blockIdx.x, s = blockIdx.y, d = blockIdx.z;
    const int k0 = c * LCH;
    __nv_bfloat16* Th = g_Th + (size_t)c * 256 * 320;
    __nv_bfloat16* Tl = g_Tl + (size_t)c * 256 * 320;

    const float* src0 = ((d == 0) ? B : F) + (size_t)(k0 + s) * 512;
    for (int e = tid; e < 512; e += 128) sV[0][e >> 4][e & 15] = src0[e];
    if (d == 0) {
        const float* Ds = D + (size_t)(k0 + s) * 256;
        for (int e = tid; e < 256; e += 128) {
            const int o = e >> 4, i = e & 15;
            __nv_bfloat16 h, l; split_bf16(Ds[o * 16 + i], h, l);
            const size_t idx = (size_t)(s * 16 + o) * 320 + s * 16 + i;
            Th[idx] = h; Tl[idx] = l;
        }
    }
    __syncthreads();

    int pb = 0;
    const int nsteps = (d == 0) ? (LCH - 1 - s) : s;
    for (int step = 0; step < nsteps; ++step) {
        const int t = (d == 0) ? (s + 1 + step) : (s - 1 - step);
        const int k = k0 + t;
        const float* W2 = ((d == 0) ? A : E) + (size_t)k * 1024;
        const float* W1 = ((d == 0) ? C : G) + (size_t)k * 512;
        for (int e = tid; e < 1024; e += 128) sW2[e >> 5][e & 31] = W2[e];
        for (int e = tid; e < 512;  e += 128) sW1[e >> 5][e & 31] = W1[e];
        __syncthreads();
        for (int e = tid; e < 256; e += 128) {
            const int o = e >> 4, i = e & 15;
            float acc = 0.f;
#pragma unroll
            for (int l = 0; l < DS; ++l) acc += sW1[o][l] * sV[pb][l][i];
            __nv_bfloat16 h, l2; split_bf16(acc, h, l2);
            const size_t idx = (size_t)(t * 16 + o) * 320 + s * 16 + i;
            Th[idx] = h; Tl[idx] = l2;
        }
        for (int e = tid; e < 512; e += 128) {
            const int j = e >> 4, i = e & 15;
            float acc = 0.f;
#pragma unroll
            for (int l = 0; l < DS; ++l) acc += sW2[j][l] * sV[pb][l][i];
            sV[pb ^ 1][j][i] = acc;
        }
        __syncthreads();
        pb ^= 1;
    }
    for (int e = tid; e < 512; e += 128) {
        const int j = e >> 4, i = e & 15;
        __nv_bfloat16 h, l; split_bf16(sV[pb][j][i], h, l);
        const size_t idx = (size_t)c * 64 * 256 + (size_t)(d * 32 + j) * 256 + s * 16 + i;
        g_Sh[idx] = h; g_Sl[idx] = l;
    }
}

// =====================================================================
// 3. M/N correction rows of T^T + propagators
// =====================================================================
__global__ __launch_bounds__(256)
void mn_kernel(const float* __restrict__ A, const float* __restrict__ C,
               const float* __restrict__ E, const float* __restrict__ G) {
    __shared__ float sV[2][DS][DS];
    __shared__ float sW2[DS][DS];
    __shared__ float sW1[IO][DS];
    const int tid = threadIdx.x;
    const int c = blockIdx.x, d = blockIdx.y;
    const int k0 = c * LCH;
    __nv_bfloat16* Th = g_Th + (size_t)c * 256 * 320;
    __nv_bfloat16* Tl = g_Tl + (size_t)c * 256 * 320;

    for (int e = tid; e < 1024; e += 256)
        sV[0][e >> 5][e & 31] = ((e >> 5) == (e & 31)) ? 1.f : 0.f;
    __syncthreads();

    int pb = 0;
    for (int step = 0; step < LCH; ++step) {
        const int t = (d == 0) ? step : (LCH - 1 - step);
        const int k = k0 + t;
        const float* W2 = ((d == 0) ? A : E) + (size_t)k * 1024;
        const float* W1 = ((d == 0) ? C : G) + (size_t)k * 512;
        for (int e = tid; e < 1024; e += 256) sW2[e >> 5][e & 31] = W2[e];
        for (int e = tid; e < 512;  e += 256) sW1[e >> 5][e & 31] = W1[e];
        __syncthreads();
        for (int e = tid; e < 512; e += 256) {
            const int o = e >> 5, j = e & 31;
            float acc = 0.f;
#pragma unroll
            for (int l = 0; l < DS; ++l) acc += sW1[o][l] * sV[pb][l][j];
            __nv_bfloat16 h, l2; split_bf16(acc, h, l2);
            const size_t idx = (size_t)(t * 16 + o) * 320 + 256 + d * 32 + j;
            Th[idx] = h; Tl[idx] = l2;
        }
        for (int e = tid; e < 1024; e += 256) {
            const int i = e >> 5, j = e & 31;
            float acc = 0.f;
#pragma unroll
            for (int l = 0; l < DS; ++l) acc += sW2[i][l] * sV[pb][l][j];
            sV[pb ^ 1][i][j] = acc;
        }
        __syncthreads();
        pb ^= 1;
    }
    for (int e = tid; e < 1024; e += 256) {
        const int i = e >> 5, j = e & 31;
        g_P2[(size_t)(d * NCH + c) * 1024 + j * 32 + i] = sV[pb][i][j];
    }
}

// =====================================================================
// 4. GEMM1 (mma.sync): xloc[128x64] = A[128x256] x S^T, split-bf16
//    stage (48KB): Ah 16K | Al 16K | Bh 8K | Bl 8K, 2 stages
//    128 thr = 4 warps (2m x 2n), warp tile 64x32
// =====================================================================
__global__ __launch_bounds__(128)
void gemm1_kernel() {
    extern __shared__ char smem[];
    const uint32_t sb = (uint32_t)__cvta_generic_to_shared(smem);
    const int tid = threadIdx.x, wid = tid >> 5, lane = tid & 31;
    const int mt = blockIdx.x, c = blockIdx.y;
    const int row0 = mt * 128;
    const int wm = wid & 1, wn = wid >> 1;
    const int mbase = wm * 64, nbase = wn * 32;

    auto load_stage = [&](int st, int kt) {
        char* base = smem + st * 49152;
#pragma unroll
        for (int q = 0; q < 8; ++q) {
            const int i = tid + 128 * q, r = i >> 3, k8 = i & 7;
            const uint32_t o = swz(r, k8);
            const size_t g = (size_t)(row0 + r) * PTOT + c * 256 + kt * 64 + k8 * 8;
            cpasync16(base + o, g_Uh + g);
            cpasync16(base + 16384 + o, g_Ul + g);
        }
#pragma unroll
        for (int q = 0; q < 4; ++q) {
            const int i = tid + 128 * q, r = i >> 3, k8 = i & 7;
            const uint32_t o = swz(r, k8);
            const size_t g = (size_t)c * 64 * 256 + (size_t)r * 256 + kt * 64 + k8 * 8;
            cpasync16(base + 32768 + o, g_Sh + g);
            cpasync16(base + 40960 + o, g_Sl + g);
        }
    };

    float acc[4][4][4];
#pragma unroll
    for (int mi = 0; mi < 4; ++mi)
#pragma unroll
        for (int ni = 0; ni < 4; ++ni)
#pragma unroll
            for (int q = 0; q < 4; ++q) acc[mi][ni][q] = 0.f;

    load_stage(0, 0); cpcommit();
    load_stage(1, 1); cpcommit();

    const int atile = lane >> 3;                   // 0..3
    const int ar_off = (lane & 7) + (atile & 1) * 8;
    const int ak_off = atile >> 1;                 // 0/1 (16B chunk within k16)
    const int btt = lane & 15;
    const int br_off = btt & 7;
    const int bk_off = btt >> 3;

#pragma unroll 1
    for (int kt = 0; kt < 4; ++kt) {
        const int st = kt & 1;
        cpwait<1>(); __syncthreads();
        const uint32_t tb = sb + st * 49152;
#pragma unroll
        for (int ks = 0; ks < 4; ++ks) {
            uint32_t bh[4][2], bl[4][2];
#pragma unroll
            for (int ni = 0; ni < 4; ++ni) {
                const int r = nbase + ni * 8 + br_off;
                const uint32_t o = swz(r, 2 * ks + bk_off);
                ldmx2(bh[ni], tb + 32768 + o);
                ldmx2(bl[ni], tb + 40960 + o);
            }
#pragma unroll
            for (int mi = 0; mi < 4; ++mi) {
                const int r = mbase + mi * 16 + ar_off;
                const uint32_t o = swz(r, 2 * ks + ak_off);
                uint32_t ah[4], al[4];
                ldmx4(ah, tb + o);
                ldmx4(al, tb + 16384 + o);
#pragma unroll
                for (int ni = 0; ni < 4; ++ni) {
                    mma16816(acc[mi][ni], ah, bh[ni]);
                    mma16816(acc[mi][ni], ah, bl[ni]);
                    mma16816(acc[mi][ni], al, bh[ni]);
                }
            }
        }
        __syncthreads();
        if (kt < 2) load_stage(st, kt + 2);
        cpcommit();
    }

    // epilogue -> g_xloc [row][c][64]
#pragma unroll
    for (int mi = 0; mi < 4; ++mi) {
        const int r0 = row0 + mbase + mi * 16 + (lane >> 2);
#pragma unroll
        for (int ni = 0; ni < 4; ++ni) {
            const int n = nbase + ni * 8 + (lane & 3) * 2;
            float* d0 = g_xloc + ((size_t)r0 * NCH + c) * 64 + n;
            float* d1 = g_xloc + ((size_t)(r0 + 8) * NCH + c) * 64 + n;
            *(float2*)d0 = make_float2(acc[mi][ni][0], acc[mi][ni][1]);
            *(float2*)d1 = make_float2(acc[mi][ni][2], acc[mi][ni][3]);
        }
    }
}

// =====================================================================
// 5. Phase B: chunk recombination, one thread per row; emits xin bf16 h/l
// =====================================================================
__global__ __launch_bounds__(64)
void phaseB_kernel() {
    __shared__ float sP[DS * DS];
    const int tid = threadIdx.x;
    const int d = blockIdx.y;
    const int row = blockIdx.x * 64 + tid;

    ull xp[16];
#pragma unroll
    for (int ip = 0; ip < 16; ++ip) xp[ip] = 0;

#pragma unroll 1
    for (int ci = 0; ci < NCH; ++ci) {
        const int c = d ? (NCH - 1 - ci) : ci;
        __syncthreads();
        {
            const float4* src = (const float4*)(g_P2 + (size_t)(d * NCH + c) * 1024);
#pragma unroll
            for (int q = 0; q < 4; ++q) ((float4*)sP)[tid + 64 * q] = src[tid + 64 * q];
        }
        __syncthreads();

        float x[DS];
        const size_t xoff = ((size_t)row * NCH + c) * 64 + d * 32;
#pragma unroll
        for (int ip = 0; ip < 16; ++ip) {
            unpack2(xp[ip], x[2 * ip], x[2 * ip + 1]);
            __nv_bfloat16 h0, l0, h1, l1;
            split_bf16(x[2 * ip], h0, l0);
            split_bf16(x[2 * ip + 1], h1, l1);
            ((__nv_bfloat162*)(g_xinh + xoff))[ip] = __nv_bfloat162(h0, h1);
            ((__nv_bfloat162*)(g_xinl + xoff))[ip] = __nv_bfloat162(l0, l1);
        }

        ull acc[16];
        {
            const float4* xl = (const float4*)(g_xloc + xoff);
#pragma unroll
            for (int q = 0; q < 8; ++q) {
                float4 v = xl[q];
                acc[2 * q]     = pack2(v.x, v.y);
                acc[2 * q + 1] = pack2(v.z, v.w);
            }
        }
#pragma unroll
        for (int j = 0; j < DS; ++j) {
            const ull xx = dup2(x[j]);
            const ulonglong2* pr = (const ulonglong2*)&sP[j * DS];
#pragma unroll
            for (int t = 0; t < 8; ++t) {
                const ulonglong2 pv = pr[t];
                acc[2 * t]     = fma2(pv.x, xx, acc[2 * t]);
                acc[2 * t + 1] = fma2(pv.y, xx, acc[2 * t + 1]);
            }
        }
#pragma unroll
        for (int ip = 0; ip < 16; ++ip) xp[ip] = acc[ip];
    }
}

// =====================================================================
// 6. GEMM2 (mma.sync): out[128x128] = A[128x320] x T^T + bias, split-bf16
//    stage (64KB): Ah 16K | Al 16K | Bh 16K | Bl 16K, 2 stages
//    256 thr = 8 warps (2m x 4n), warp tile 64x32
// =====================================================================
__global__ __launch_bounds__(256)
void gemm2_kernel(const float* __restrict__ bias, float* __restrict__ out) {
    extern __shared__ char smem[];
    const uint32_t sb = (uint32_t)__cvta_generic_to_shared(smem);
    const int tid = threadIdx.x, wid = tid >> 5, lane = tid & 31;
    const int mt = blockIdx.x, nt = blockIdx.y, c = blockIdx.z;
    const int row0 = mt * 128, nc = nt * 128;
    const int wm = wid & 1, wn = wid >> 1;
    const int mbase = wm * 64, nbase = wn * 32;

    auto load_stage = [&](int st, int kt) {
        char* base = smem + st * 65536;
#pragma unroll
        for (int q = 0; q < 4; ++q) {
            const int i = tid + 256 * q, r = i >> 3, k8 = i & 7;
            const uint32_t o = swz(r, k8);
            const __nv_bfloat16 *sh, *sl;
            if (kt < 4) {
                const size_t g = (size_t)(row0 + r) * PTOT + c * 256 + kt * 64 + k8 * 8;
                sh = g_Uh + g; sl = g_Ul + g;
            } else {
                const size_t g = ((size_t)(row0 + r) * NCH + c) * 64 + k8 * 8;
                sh = g_xinh + g; sl = g_xinl + g;
            }
            cpasync16(base + o, sh);
            cpasync16(base + 16384 + o, sl);
        }
#pragma unroll
        for (int q = 0; q < 4; ++q) {
            const int i = tid + 256 * q, r = i >> 3, k8 = i & 7;
            const uint32_t o = swz(r, k8);
            const size_t g = (size_t)c * 256 * 320 + (size_t)(nc + r) * 320 + kt * 64 + k8 * 8;
            cpasync16(base + 32768 + o, g_Th + g);
            cpasync16(base + 49152 + o, g_Tl + g);
        }
    };

    float acc[4][4][4];
#pragma unroll
    for (int mi = 0; mi < 4; ++mi)
#pragma unroll
        for (int ni = 0; ni < 4; ++ni)
#pragma unroll
            for (int q = 0; q < 4; ++q) acc[mi][ni][q] = 0.f;

    load_stage(0, 0); cpcommit();
    load_stage(1, 1); cpcommit();

    const int atile = lane >> 3;
    const int ar_off = (lane & 7) + (atile & 1) * 8;
    const int ak_off = atile >> 1;
    const int btt = lane & 15;
    const int br_off = btt & 7;
    const int bk_off = btt >> 3;

#pragma unroll 1
    for (int kt = 0; kt < 5; ++kt) {
        const int st = kt & 1;
        cpwait<1>(); __syncthreads();
        const uint32_t tb = sb + st * 65536;
#pragma unroll
        for (int ks = 0; ks < 4; ++ks) {
            uint32_t bh[4][2], bl[4][2];
#pragma unroll
            for (int ni = 0; ni < 4; ++ni) {
                const int r = nbase + ni * 8 + br_off;
                const uint32_t o = swz(r, 2 * ks + bk_off);
                ldmx2(bh[ni], tb + 32768 + o);
                ldmx2(bl[ni], tb + 49152 + o);
            }
#pragma unroll
            for (int mi = 0; mi < 4; ++mi) {
                const int r = mbase + mi * 16 + ar_off;
                const uint32_t o = swz(r, 2 * ks + ak_off);
                uint32_t ah[4], al[4];
                ldmx4(ah, tb + o);
                ldmx4(al, tb + 16384 + o);
#pragma unroll
                for (int ni = 0; ni < 4; ++ni) {
                    mma16816(acc[mi][ni], ah, bh[ni]);
                    mma16816(acc[mi][ni], ah, bl[ni]);
                    mma16816(acc[mi][ni], al, bh[ni]);
                }
            }
        }
        __syncthreads();
        if (kt < 3) load_stage(st, kt + 2);
        cpcommit();
    }

    // epilogue: + bias, store float2 per tile-row
#pragma unroll
    for (int mi = 0; mi < 4; ++mi) {
        const int r0 = row0 + mbase + mi * 16 + (lane >> 2);
#pragma unroll
        for (int ni = 0; ni < 4; ++ni) {
            const int n = nc + nbase + ni * 8 + (lane & 3) * 2;
            const float2 bv = *(const float2*)(bias + c * 256 + n);
            float* d0 = out + (size_t)r0 * PTOT + c * 256 + n;
            float* d1 = out + (size_t)(r0 + 8) * PTOT + c * 256 + n;
            *(float2*)d0 = make_float2(acc[mi][ni][0] + bv.x, acc[mi][ni][1] + bv.y);
            *(float2*)d1 = make_float2(acc[mi][ni][2] + bv.x, acc[mi][ni][3] + bv.y);
        }
    }
}

// =====================================================================
extern "C" void kernel_launch(void* const* d_in, const int* in_sizes, int n_in,
                              void* d_out, int out_size) {
    const float* U    = (const float*)d_in[0];
    const float* A    = (const float*)d_in[1];
    const float* B    = (const float*)d_in[2];
    const float* C    = (const float*)d_in[3];
    const float* D    = (const float*)d_in[4];
    const float* E    = (const float*)d_in[5];
    const float* F    = (const float*)d_in[6];
    const float* G    = (const float*)d_in[7];
    const float* bias = (const float*)d_in[8];
    float* out = (float*)d_out;

    cudaFuncSetAttribute(gemm1_kernel, cudaFuncAttributeMaxDynamicSharedMemorySize, 2 * 49152);
    cudaFuncSetAttribute(gemm2_kernel, cudaFuncAttributeMaxDynamicSharedMemorySize, 2 * 65536);

    convertU_kernel<<<(BATCH * PTOT / 4) / 256, 256>>>(U);
    strip_kernel<<<dim3(NCH, LCH, 2), 128>>>(A, B, C, D, E, F, G);
    mn_kernel<<<dim3(NCH, 2), 256>>>(A, C, E, G);
    gemm1_kernel<<<dim3(BATCH / 128, NCH), 128, 2 * 49152>>>();
    phaseB_kernel<<<dim3(BATCH / 64, 2), 64>>>();
    gemm2_kernel<<<dim3(BATCH / 128, 2, NCH), 256, 2 * 65536>>>(bias, out);
}